// round 2
// baseline (speedup 1.0000x reference)
#include <cuda_runtime.h>
#include <math.h>

// Problem constants
#define Bc 32
#define Nc 512
#define Dc 512
#define Ec 8
#define Pc 96
#define Kc 25
#define Hc 4
#define DKc 128
#define PADc 12
#define BNc (Bc * Nc)   // 16384

// ---------------- scratch (device globals; no allocation allowed) -------------
__device__ float g_q[Ec * Dc];            // router projection (batch-invariant)
__device__ float g_k[(size_t)BNc * Dc];   // keys   [B,N,D]
__device__ float g_v[(size_t)BNc * Dc];   // values [B,N,D]
__device__ float g_att[Bc * Ec * Dc];     // attention out (pre-Wo)
__device__ float g_atto[Bc * Ec * Dc];    // att @ Wo + bo
__device__ float g_norm[Bc * Ec];         // ||atto row||
__device__ int   g_idx[BNc];              // chosen expert per token

// ---------------- K1: q = router @ Wq + bq  (per-expert, batch-invariant) ----
__global__ __launch_bounds__(512) void k1_qproj(const float* __restrict__ router,
                                                const float* __restrict__ Wq,
                                                const float* __restrict__ bq) {
    int e = blockIdx.x;
    int j = threadIdx.x;           // 0..511
    __shared__ float rr[Dc];
    rr[j] = router[e * Dc + j];
    __syncthreads();
    float acc = bq[j];
    #pragma unroll 4
    for (int d = 0; d < Dc; d++) acc += rr[d] * Wq[(size_t)d * Dc + j];
    g_q[e * Dc + j] = acc;
}

// ---------------- K2: K = x@Wk + bk ; V = x@Wv + bv  (fused tiled GEMM) -----
#define TBM 64
#define TBN 64
#define TBK 16
__global__ __launch_bounds__(256) void k2_kv(const float* __restrict__ x,
                                             const float* __restrict__ Wk,
                                             const float* __restrict__ bk,
                                             const float* __restrict__ Wv,
                                             const float* __restrict__ bv) {
    __shared__ float sX[TBK][TBM + 4];
    __shared__ float sK[TBK][TBN];
    __shared__ float sV[TBK][TBN];
    int m0 = blockIdx.y * TBM;
    int j0 = blockIdx.x * TBN;
    int tid = threadIdx.x;
    int tx = tid & 15, ty = tid >> 4;

    float aK[4][4] = {}, aV[4][4] = {};

    for (int kk = 0; kk < Dc; kk += TBK) {
        // x tile: 64 rows x 16 cols, stored transposed
        {
            int c = tid & 15, r4 = tid >> 4;
            #pragma unroll
            for (int p = 0; p < 4; p++) {
                int r = r4 + p * 16;
                sX[c][r] = x[(size_t)(m0 + r) * Dc + kk + c];
            }
        }
        // W tiles: 16 rows x 64 cols
        {
            int c = tid & 63, r4 = tid >> 6;
            #pragma unroll
            for (int p = 0; p < 4; p++) {
                int r = r4 + p * 4;
                sK[r][c] = Wk[(size_t)(kk + r) * Dc + j0 + c];
                sV[r][c] = Wv[(size_t)(kk + r) * Dc + j0 + c];
            }
        }
        __syncthreads();
        #pragma unroll
        for (int k = 0; k < TBK; k++) {
            float a[4], fk[4], fv[4];
            #pragma unroll
            for (int i = 0; i < 4; i++) a[i] = sX[k][ty * 4 + i];
            #pragma unroll
            for (int j = 0; j < 4; j++) { fk[j] = sK[k][tx * 4 + j]; fv[j] = sV[k][tx * 4 + j]; }
            #pragma unroll
            for (int i = 0; i < 4; i++)
                #pragma unroll
                for (int j = 0; j < 4; j++) {
                    aK[i][j] += a[i] * fk[j];
                    aV[i][j] += a[i] * fv[j];
                }
        }
        __syncthreads();
    }
    #pragma unroll
    for (int i = 0; i < 4; i++) {
        int row = m0 + ty * 4 + i;
        #pragma unroll
        for (int j = 0; j < 4; j++) {
            int col = j0 + tx * 4 + j;
            g_k[(size_t)row * Dc + col] = aK[i][j] + bk[col];
            g_v[(size_t)row * Dc + col] = aV[i][j] + bv[col];
        }
    }
}

// ---------------- K3: attention per (b,e,h): scores->softmax->weighted V ----
__global__ __launch_bounds__(128) void k3_attn() {
    int e = blockIdx.x, h = blockIdx.y, b = blockIdx.z;
    int tid = threadIdx.x, lane = tid & 31, warp = tid >> 5;
    __shared__ float qv[DKc];
    __shared__ float sc[Nc];
    __shared__ float red[128];

    qv[tid] = g_q[e * Dc + h * DKc + tid];
    __syncthreads();

    const float scale = 0.08838834764831845f;  // 1/sqrt(128)
    // scores: each warp handles strided n
    for (int n = warp; n < Nc; n += 4) {
        const float* kr = g_k + ((size_t)b * Nc + n) * Dc + h * DKc;
        float p = 0.f;
        #pragma unroll
        for (int j = lane; j < DKc; j += 32) p += qv[j] * kr[j];
        #pragma unroll
        for (int o = 16; o > 0; o >>= 1) p += __shfl_down_sync(0xffffffffu, p, o);
        if (lane == 0) sc[n] = p * scale;
    }
    __syncthreads();

    // softmax over 512
    float m = -INFINITY;
    #pragma unroll
    for (int n = tid; n < Nc; n += 128) m = fmaxf(m, sc[n]);
    red[tid] = m; __syncthreads();
    for (int s = 64; s > 0; s >>= 1) { if (tid < s) red[tid] = fmaxf(red[tid], red[tid + s]); __syncthreads(); }
    float M = red[0]; __syncthreads();

    float ssum = 0.f;
    #pragma unroll
    for (int n = tid; n < Nc; n += 128) { float ev = expf(sc[n] - M); sc[n] = ev; ssum += ev; }
    red[tid] = ssum; __syncthreads();
    for (int s = 64; s > 0; s >>= 1) { if (tid < s) red[tid] += red[tid + s]; __syncthreads(); }
    float inv = 1.0f / red[0]; __syncthreads();
    #pragma unroll
    for (int n = tid; n < Nc; n += 128) sc[n] *= inv;
    __syncthreads();

    // out[j] = sum_n A[n] * v[b,n,h*128+j]
    const float* vb = g_v + (size_t)b * Nc * Dc + h * DKc + tid;
    float a0 = 0, a1 = 0, a2 = 0, a3 = 0;
    for (int n = 0; n < Nc; n += 4) {
        a0 += sc[n + 0] * vb[(size_t)(n + 0) * Dc];
        a1 += sc[n + 1] * vb[(size_t)(n + 1) * Dc];
        a2 += sc[n + 2] * vb[(size_t)(n + 2) * Dc];
        a3 += sc[n + 3] * vb[(size_t)(n + 3) * Dc];
    }
    g_att[(b * Ec + e) * Dc + h * DKc + tid] = (a0 + a1) + (a2 + a3);
}

// ---------------- K4: atto = att @ Wo + bo, plus row norm --------------------
__global__ __launch_bounds__(256) void k4_oproj(const float* __restrict__ Wo,
                                                const float* __restrict__ bo) {
    int row = blockIdx.x;   // b*E + e
    int tid = threadIdx.x;
    __shared__ float s[Dc];
    __shared__ float red[256];
    s[tid]       = g_att[row * Dc + tid];
    s[tid + 256] = g_att[row * Dc + 256 + tid];
    __syncthreads();
    float o0 = bo[tid], o1 = bo[tid + 256];
    #pragma unroll 4
    for (int d = 0; d < Dc; d++) {
        float sv = s[d];
        o0 += sv * Wo[(size_t)d * Dc + tid];
        o1 += sv * Wo[(size_t)d * Dc + tid + 256];
    }
    g_atto[row * Dc + tid]       = o0;
    g_atto[row * Dc + tid + 256] = o1;
    red[tid] = o0 * o0 + o1 * o1;
    __syncthreads();
    for (int sft = 128; sft > 0; sft >>= 1) { if (tid < sft) red[tid] += red[tid + sft]; __syncthreads(); }
    if (tid == 0) g_norm[row] = sqrtf(red[0]);
}

// ---------------- K5: routing argmax (norm_x cancels) ------------------------
#define TOKS 16
__global__ __launch_bounds__(128) void k5_route(const float* __restrict__ x) {
    int b = blockIdx.y;
    int n0 = blockIdx.x * TOKS;
    int tid = threadIdx.x;
    __shared__ float s_att[Ec][516];
    __shared__ float s_norm[Ec];
    __shared__ float s_dot[TOKS][Ec + 1];

    for (int i = tid; i < Ec * Dc; i += 128) {
        int e = i >> 9, d = i & 511;
        s_att[e][d] = g_atto[(b * Ec + e) * Dc + d];
    }
    if (tid < Ec) s_norm[tid] = g_norm[b * Ec + tid];
    __syncthreads();

    int tok = tid >> 3, e = tid & 7;
    const float* xr = x + ((size_t)b * Nc + n0 + tok) * Dc;
    const float* ar = s_att[e];
    float c0 = 0, c1 = 0, c2 = 0, c3 = 0;
    for (int d = 0; d < Dc; d += 4) {
        c0 += xr[d + 0] * ar[d + 0];
        c1 += xr[d + 1] * ar[d + 1];
        c2 += xr[d + 2] * ar[d + 2];
        c3 += xr[d + 3] * ar[d + 3];
    }
    s_dot[tok][e] = (c0 + c1) + (c2 + c3);
    __syncthreads();

    if (tid < TOKS) {
        float best = -INFINITY; int bi = 0;
        #pragma unroll
        for (int ee = 0; ee < Ec; ee++) {
            float v = s_dot[tid][ee] / s_norm[ee];
            if (v > best) { best = v; bi = ee; }   // first-max, matches jnp.argmax
        }
        g_idx[b * Nc + n0 + tid] = bi;
    }
}

// ---------------- K6: gathered expert conv1d(K=25) + linear(512->96) ---------
__global__ __launch_bounds__(128) void k6_expert(const float* __restrict__ x,
                                                 const float* __restrict__ Wc,
                                                 const float* __restrict__ bc,
                                                 const float* __restrict__ Wp,
                                                 const float* __restrict__ bp,
                                                 float* __restrict__ out) {
    int t = blockIdx.x;            // token id in [0, BN)
    int b = t >> 9;
    int tid = threadIdx.x;
    int e = g_idx[t];

    __shared__ float xp[Dc + 2 * PADc];   // 536
    __shared__ float zp[Dc + 2 * PADc];
    __shared__ float cv[Dc];
    __shared__ float wc[2 * Kc];
    __shared__ float s_bc;

    const float* xr = x + (size_t)t * Dc;
    const float* zr = g_atto + (b * Ec + e) * Dc;
    for (int i = tid; i < Dc + 2 * PADc; i += 128) {
        bool in = (i >= PADc) && (i < Dc + PADc);
        xp[i] = in ? xr[i - PADc] : 0.f;
        zp[i] = in ? zr[i - PADc] : 0.f;
    }
    if (tid < 2 * Kc) wc[tid] = Wc[e * 2 * Kc + tid];
    if (tid == 0) s_bc = bc[e];
    __syncthreads();

    for (int l = tid; l < Dc; l += 128) {
        float acc = s_bc;
        #pragma unroll
        for (int k = 0; k < Kc; k++)
            acc += wc[k] * xp[l + k] + wc[Kc + k] * zp[l + k];
        cv[l] = acc;
    }
    __syncthreads();

    if (tid < Pc) {
        const float* wp = Wp + (size_t)e * Dc * Pc + tid;
        float a0 = bp[e * Pc + tid], a1 = 0, a2 = 0, a3 = 0;
        for (int l = 0; l < Dc; l += 4) {
            a0 += cv[l + 0] * wp[(size_t)(l + 0) * Pc];
            a1 += cv[l + 1] * wp[(size_t)(l + 1) * Pc];
            a2 += cv[l + 2] * wp[(size_t)(l + 2) * Pc];
            a3 += cv[l + 3] * wp[(size_t)(l + 3) * Pc];
        }
        out[(size_t)t * Pc + tid] = (a0 + a1) + (a2 + a3);
    }
}

// ---------------- launcher ---------------------------------------------------
extern "C" void kernel_launch(void* const* d_in, const int* in_sizes, int n_in,
                              void* d_out, int out_size) {
    const float* x      = (const float*)d_in[0];
    const float* router = (const float*)d_in[1];
    const float* Wq     = (const float*)d_in[2];
    const float* bq     = (const float*)d_in[3];
    const float* Wk     = (const float*)d_in[4];
    const float* bk     = (const float*)d_in[5];
    const float* Wv     = (const float*)d_in[6];
    const float* bv     = (const float*)d_in[7];
    const float* Wo     = (const float*)d_in[8];
    const float* bo     = (const float*)d_in[9];
    const float* Wc     = (const float*)d_in[10];
    const float* bc     = (const float*)d_in[11];
    const float* Wp     = (const float*)d_in[12];
    const float* bp     = (const float*)d_in[13];
    float* out = (float*)d_out;

    // K1: router projection (batch-invariant)
    k1_qproj<<<Ec, 512>>>(router, Wq, bq);
    // K2: fused K/V GEMMs
    dim3 g2(Dc / TBN, BNc / TBM);
    k2_kv<<<g2, 256>>>(x, Wk, bk, Wv, bv);
    // K3: attention
    dim3 g3(Ec, Hc, Bc);
    k3_attn<<<g3, 128>>>();
    // K4: output projection + row norms
    k4_oproj<<<Bc * Ec, 256>>>(Wo, bo);
    // K5: routing argmax
    dim3 g5(Nc / TOKS, Bc);
    k5_route<<<g5, 128>>>(x);
    // K6: gathered expert conv + linear
    k6_expert<<<BNc, 128>>>(x, Wc, bc, Wp, bp, out);
}

// round 4
// speedup vs baseline: 2.0510x; 2.0510x over previous
#include <cuda_runtime.h>
#include <math.h>

// Problem constants
#define Bc 32
#define Nc 512
#define Dc 512
#define Ec 8
#define Pc 96
#define Kc 25
#define Hc 4
#define DKc 128
#define PADc 12
#define BNc (Bc * Nc)   // 16384
#define EHc 32          // E*H

// ---------------- scratch (device globals; no allocation allowed) -------------
__device__ float g_q[Ec * Dc];               // router projection (batch-invariant)
__device__ float g_qkT[Dc * EHc];            // Wk_h @ q_eh, transposed [d][eh]
__device__ float g_qb[EHc];                  // q_eh . bk_h
__device__ float g_sc[(size_t)Bc * EHc * Nc];// scores then softmax A  [b][eh][n]
__device__ float g_y[(size_t)Bc * EHc * Dc]; // y = A @ X              [b][eh][d]
__device__ float g_att[Bc * Ec * Dc];        // attention out (pre-Wo)
__device__ float g_atto[Bc * Ec * Dc];       // att @ Wo + bo
__device__ float g_norm[Bc * Ec];            // ||atto row||
__device__ int   g_idx[BNc];                 // chosen expert per token
__device__ float g_cv[(size_t)BNc * Dc];     // conv output per token
__device__ int   g_blkcnt[64 * Ec];
__device__ int   g_blkoff[64 * Ec];
__device__ int   g_off[Ec + 1];
__device__ int   g_tok[BNc];                 // token list grouped by expert

// ---------------- K1: q = router @ Wq + bq  (batch-invariant) ----------------
__global__ __launch_bounds__(512) void k1_qproj(const float* __restrict__ router,
                                                const float* __restrict__ Wq,
                                                const float* __restrict__ bq) {
    int e = blockIdx.x;
    int j = threadIdx.x;
    __shared__ float rr[Dc];
    rr[j] = router[e * Dc + j];
    __syncthreads();
    float acc = bq[j];
    #pragma unroll 4
    for (int d = 0; d < Dc; d++) acc += rr[d] * Wq[(size_t)d * Dc + j];
    g_q[e * Dc + j] = acc;
}

// ---------------- K2: qk[d][eh] = sum_dk Wk[d, h*128+dk] * q[e, h*128+dk] ----
__global__ __launch_bounds__(256) void k2_qk(const float* __restrict__ Wk,
                                             const float* __restrict__ bk) {
    int eh = blockIdx.x;          // e*4 + h
    int e = eh >> 2, h = eh & 3;
    int tid = threadIdx.x, lane = tid & 31, warp = tid >> 5;
    __shared__ float sq[DKc];
    __shared__ float red[128];
    if (tid < DKc) sq[tid] = g_q[e * Dc + h * DKc + tid];
    __syncthreads();
    // rows d, 8 warps
    for (int d = warp; d < Dc; d += 8) {
        const float* wr = Wk + (size_t)d * Dc + h * DKc;
        float p = 0.f;
        #pragma unroll
        for (int j = 0; j < 4; j++) p += wr[lane + j * 32] * sq[lane + j * 32];
        #pragma unroll
        for (int o = 16; o > 0; o >>= 1) p += __shfl_down_sync(0xffffffffu, p, o);
        if (lane == 0) g_qkT[d * EHc + eh] = p;
    }
    // qb
    if (tid < DKc) red[tid] = sq[tid] * bk[h * DKc + tid];
    __syncthreads();
    if (tid < 64 && tid + 64 < DKc) red[tid] += red[tid + 64];
    __syncthreads();
    if (tid < 32) {
        float v = red[tid] + red[tid + 32];
        #pragma unroll
        for (int o = 16; o > 0; o >>= 1) v += __shfl_down_sync(0xffffffffu, v, o);
        if (tid == 0) g_qb[eh] = v;
    }
}

// ---------------- K3: scores = X @ QK + qb, *scale  (GEMM 16384x32x512) ------
__global__ __launch_bounds__(256) void k3_scores(const float* __restrict__ x) {
    __shared__ float sX[64][129];     // [k][tok]
    __shared__ float sQ[64][32];      // [k][eh]
    __shared__ float sQB[EHc];
    int t0 = blockIdx.x * 128;
    int b = t0 >> 9, n0 = t0 & 511;
    int tid = threadIdx.x;
    if (tid < EHc) sQB[tid] = g_qb[tid];
    int ty = tid >> 3, tx = tid & 7;  // ty:0..31 (4 tokens), tx:0..7 (4 eh)
    float acc[4][4] = {};
    for (int kk = 0; kk < Dc; kk += 64) {
        #pragma unroll
        for (int j = 0; j < 32; j++) {
            int id = tid + j * 256;
            int tok = id >> 6, k = id & 63;
            sX[k][tok] = x[(size_t)(t0 + tok) * Dc + kk + k];
        }
        #pragma unroll
        for (int j = 0; j < 8; j++) {
            int id = tid + j * 256;
            int k = id >> 5, eh = id & 31;
            sQ[k][eh] = g_qkT[(size_t)(kk + k) * EHc + eh];
        }
        __syncthreads();
        #pragma unroll
        for (int k = 0; k < 64; k++) {
            float a[4], q[4];
            #pragma unroll
            for (int i = 0; i < 4; i++) a[i] = sX[k][ty * 4 + i];
            #pragma unroll
            for (int j = 0; j < 4; j++) q[j] = sQ[k][tx * 4 + j];
            #pragma unroll
            for (int i = 0; i < 4; i++)
                #pragma unroll
                for (int j = 0; j < 4; j++) acc[i][j] += a[i] * q[j];
        }
        __syncthreads();
    }
    const float scale = 0.08838834764831845f;  // 1/sqrt(128)
    #pragma unroll
    for (int i = 0; i < 4; i++) {
        int n = n0 + ty * 4 + i;
        #pragma unroll
        for (int j = 0; j < 4; j++) {
            int eh = tx * 4 + j;
            g_sc[((size_t)b * EHc + eh) * Nc + n] = (acc[i][j] + sQB[eh]) * scale;
        }
    }
}

// ---------------- K4: softmax over n per (b,eh), in place --------------------
__global__ __launch_bounds__(256) void k4_softmax() {
    int row = blockIdx.x;   // b*32 + eh
    int tid = threadIdx.x;
    __shared__ float red[256];
    float v0 = g_sc[(size_t)row * Nc + tid];
    float v1 = g_sc[(size_t)row * Nc + 256 + tid];
    red[tid] = fmaxf(v0, v1);
    __syncthreads();
    for (int s = 128; s > 0; s >>= 1) { if (tid < s) red[tid] = fmaxf(red[tid], red[tid + s]); __syncthreads(); }
    float M = red[0];
    __syncthreads();
    float e0 = expf(v0 - M), e1 = expf(v1 - M);
    red[tid] = e0 + e1;
    __syncthreads();
    for (int s = 128; s > 0; s >>= 1) { if (tid < s) red[tid] += red[tid + s]; __syncthreads(); }
    float inv = 1.0f / red[0];
    g_sc[(size_t)row * Nc + tid] = e0 * inv;
    g_sc[(size_t)row * Nc + 256 + tid] = e1 * inv;
}

// ---------------- K5: y[b][eh][d] = sum_n A[b][eh][n] X[b][n][d] -------------
__global__ __launch_bounds__(256) void k5_y(const float* __restrict__ x) {
    __shared__ float sA[32][33];      // [eh][n]
    __shared__ float sX[32][128];     // [n][d]
    int d0 = blockIdx.x * 128;
    int b = blockIdx.y;
    int tid = threadIdx.x;
    int ty = tid >> 4, tx = tid & 15;  // 2 rows, 8 cols
    float acc[2][8] = {};
    for (int kk = 0; kk < Nc; kk += 32) {
        #pragma unroll
        for (int j = 0; j < 4; j++) {
            int id = tid + j * 256;
            int eh = id >> 5, n = id & 31;
            sA[eh][n] = g_sc[((size_t)b * EHc + eh) * Nc + kk + n];
        }
        #pragma unroll
        for (int j = 0; j < 16; j++) {
            int id = tid + j * 256;
            int n = id >> 7, d = id & 127;
            sX[n][d] = x[((size_t)b * Nc + kk + n) * Dc + d0 + d];
        }
        __syncthreads();
        #pragma unroll
        for (int n = 0; n < 32; n++) {
            float a0 = sA[ty * 2][n], a1 = sA[ty * 2 + 1][n];
            #pragma unroll
            for (int i = 0; i < 8; i++) {
                float xv = sX[n][tx * 8 + i];
                acc[0][i] += a0 * xv;
                acc[1][i] += a1 * xv;
            }
        }
        __syncthreads();
    }
    #pragma unroll
    for (int r = 0; r < 2; r++)
        #pragma unroll
        for (int i = 0; i < 8; i++)
            g_y[((size_t)b * EHc + ty * 2 + r) * Dc + d0 + tx * 8 + i] = acc[r][i];
}

// ---------------- K6: att = y @ Wv(head block) + bv --------------------------
__global__ __launch_bounds__(256) void k6_att(const float* __restrict__ Wv,
                                              const float* __restrict__ bv) {
    int h = blockIdx.z;
    int r0 = blockIdx.y * 64;                   // rows: b*8+e
    int c0 = h * DKc + blockIdx.x * 64;         // cols in D
    __shared__ float sY[64][33];
    __shared__ float sW[32][64];
    int tid = threadIdx.x;
    int ty = tid >> 4, tx = tid & 15;           // 4 rows, 4 cols
    float acc[4][4] = {};
    for (int kk = 0; kk < Dc; kk += 32) {
        #pragma unroll
        for (int j = 0; j < 8; j++) {
            int id = tid + j * 256;
            int r = id >> 5, k = id & 31;
            int row = r0 + r;                    // b*8+e
            sY[r][k] = g_y[((size_t)row * 4 + h) * Dc + kk + k];  // (b*32+e*4+h)
        }
        #pragma unroll
        for (int j = 0; j < 8; j++) {
            int id = tid + j * 256;
            int k = id >> 6, c = id & 63;
            sW[k][c] = Wv[(size_t)(kk + k) * Dc + c0 + c];
        }
        __syncthreads();
        #pragma unroll
        for (int k = 0; k < 32; k++) {
            float a[4], w[4];
            #pragma unroll
            for (int i = 0; i < 4; i++) a[i] = sY[ty * 4 + i][k];
            #pragma unroll
            for (int j = 0; j < 4; j++) w[j] = sW[k][tx * 4 + j];
            #pragma unroll
            for (int i = 0; i < 4; i++)
                #pragma unroll
                for (int j = 0; j < 4; j++) acc[i][j] += a[i] * w[j];
        }
        __syncthreads();
    }
    #pragma unroll
    for (int i = 0; i < 4; i++) {
        int row = r0 + ty * 4 + i;
        #pragma unroll
        for (int j = 0; j < 4; j++) {
            int col = c0 + tx * 4 + j;
            g_att[(size_t)row * Dc + col] = acc[i][j] + bv[col];
        }
    }
}

// ---------------- K7: atto = att @ Wo + bo (tiled GEMM 256x512x512) ----------
__global__ __launch_bounds__(256) void k7_oproj(const float* __restrict__ Wo,
                                                const float* __restrict__ bo) {
    int c0 = blockIdx.x * 64;
    int r0 = blockIdx.y * 64;
    __shared__ float sA[64][33];
    __shared__ float sW[32][64];
    int tid = threadIdx.x;
    int ty = tid >> 4, tx = tid & 15;
    float acc[4][4] = {};
    for (int kk = 0; kk < Dc; kk += 32) {
        #pragma unroll
        for (int j = 0; j < 8; j++) {
            int id = tid + j * 256;
            int r = id >> 5, k = id & 31;
            sA[r][k] = g_att[(size_t)(r0 + r) * Dc + kk + k];
        }
        #pragma unroll
        for (int j = 0; j < 8; j++) {
            int id = tid + j * 256;
            int k = id >> 6, c = id & 63;
            sW[k][c] = Wo[(size_t)(kk + k) * Dc + c0 + c];
        }
        __syncthreads();
        #pragma unroll
        for (int k = 0; k < 32; k++) {
            float a[4], w[4];
            #pragma unroll
            for (int i = 0; i < 4; i++) a[i] = sA[ty * 4 + i][k];
            #pragma unroll
            for (int j = 0; j < 4; j++) w[j] = sW[k][tx * 4 + j];
            #pragma unroll
            for (int i = 0; i < 4; i++)
                #pragma unroll
                for (int j = 0; j < 4; j++) acc[i][j] += a[i] * w[j];
        }
        __syncthreads();
    }
    #pragma unroll
    for (int i = 0; i < 4; i++) {
        int row = r0 + ty * 4 + i;
        #pragma unroll
        for (int j = 0; j < 4; j++) {
            int col = c0 + tx * 4 + j;
            g_atto[(size_t)row * Dc + col] = acc[i][j] + bo[col];
        }
    }
}

// ---------------- K8: row norms of atto --------------------------------------
__global__ __launch_bounds__(128) void k8_norm() {
    int row = blockIdx.x;
    int tid = threadIdx.x;
    __shared__ float red[128];
    float s = 0.f;
    #pragma unroll
    for (int j = 0; j < 4; j++) {
        float v = g_atto[(size_t)row * Dc + tid + j * 128];
        s += v * v;
    }
    red[tid] = s;
    __syncthreads();
    for (int sft = 64; sft > 0; sft >>= 1) { if (tid < sft) red[tid] += red[tid + sft]; __syncthreads(); }
    if (tid == 0) g_norm[row] = sqrtf(red[0]);
}

// ---------------- K9: routing argmax (norm_x cancels) ------------------------
#define TOKS 16
__global__ __launch_bounds__(128) void k9_route(const float* __restrict__ x) {
    int b = blockIdx.y;
    int n0 = blockIdx.x * TOKS;
    int tid = threadIdx.x;
    __shared__ float s_att[Ec][516];
    __shared__ float s_norm[Ec];
    __shared__ float s_dot[TOKS][Ec + 1];

    for (int i = tid; i < Ec * Dc; i += 128) {
        int e = i >> 9, d = i & 511;
        s_att[e][d] = g_atto[(b * Ec + e) * Dc + d];
    }
    if (tid < Ec) s_norm[tid] = g_norm[b * Ec + tid];
    __syncthreads();

    int tok = tid >> 3, e = tid & 7;
    const float* xr = x + ((size_t)b * Nc + n0 + tok) * Dc;
    const float* ar = s_att[e];
    float c0 = 0, c1 = 0, c2 = 0, c3 = 0;
    for (int d = 0; d < Dc; d += 4) {
        c0 += xr[d + 0] * ar[d + 0];
        c1 += xr[d + 1] * ar[d + 1];
        c2 += xr[d + 2] * ar[d + 2];
        c3 += xr[d + 3] * ar[d + 3];
    }
    s_dot[tok][e] = (c0 + c1) + (c2 + c3);
    __syncthreads();

    if (tid < TOKS) {
        float best = -INFINITY; int bi = 0;
        #pragma unroll
        for (int ee = 0; ee < Ec; ee++) {
            float v = s_dot[tid][ee] / s_norm[ee];
            if (v > best) { best = v; bi = ee; }   // first-max, matches jnp.argmax
        }
        g_idx[b * Nc + n0 + tid] = bi;
    }
}

// ---------------- KG: expert grouping (3 tiny kernels) -----------------------
__global__ __launch_bounds__(256) void kg1_count() {
    __shared__ int cnt[Ec];
    int j = blockIdx.x, tid = threadIdx.x;
    if (tid < Ec) cnt[tid] = 0;
    __syncthreads();
    int e = g_idx[j * 256 + tid];
    atomicAdd(&cnt[e], 1);
    __syncthreads();
    if (tid < Ec) g_blkcnt[j * Ec + tid] = cnt[tid];
}

__global__ __launch_bounds__(512) void kg2_scan() {
    __shared__ int stot[Ec];
    __shared__ int soff[Ec];
    int tid = threadIdx.x;
    if (tid < Ec) {
        int run = 0;
        for (int j = 0; j < 64; j++) {
            int c = g_blkcnt[j * Ec + tid];
            g_blkoff[j * Ec + tid] = run;
            run += c;
        }
        stot[tid] = run;
    }
    __syncthreads();
    if (tid == 0) {
        int acc = 0;
        for (int e = 0; e < Ec; e++) { soff[e] = acc; g_off[e] = acc; acc += stot[e]; }
        g_off[Ec] = acc;
    }
    __syncthreads();
    g_blkoff[tid] += soff[tid & 7];
}

__global__ __launch_bounds__(256) void kg3_scatter() {
    __shared__ int cnt[Ec];
    int j = blockIdx.x, tid = threadIdx.x;
    if (tid < Ec) cnt[tid] = 0;
    __syncthreads();
    int t = j * 256 + tid;
    int e = g_idx[t];
    int p = atomicAdd(&cnt[e], 1);
    g_tok[g_blkoff[j * Ec + e] + p] = t;
}

// ---------------- K10: conv1d(K=25) per token -> g_cv ------------------------
__global__ __launch_bounds__(128) void k10_conv(const float* __restrict__ x,
                                                const float* __restrict__ Wc,
                                                const float* __restrict__ bc) {
    int t = blockIdx.x;
    int b = t >> 9;
    int tid = threadIdx.x;
    int e = g_idx[t];

    __shared__ float xp[Dc + 2 * PADc];
    __shared__ float zp[Dc + 2 * PADc];
    __shared__ float wc[2 * Kc];
    __shared__ float s_bc;

    const float* xr = x + (size_t)t * Dc;
    const float* zr = g_atto + (b * Ec + e) * Dc;
    for (int i = tid; i < Dc + 2 * PADc; i += 128) {
        bool in = (i >= PADc) && (i < Dc + PADc);
        xp[i] = in ? xr[i - PADc] : 0.f;
        zp[i] = in ? zr[i - PADc] : 0.f;
    }
    if (tid < 2 * Kc) wc[tid] = Wc[e * 2 * Kc + tid];
    if (tid == 0) s_bc = bc[e];
    __syncthreads();

    #pragma unroll
    for (int jj = 0; jj < 4; jj++) {
        int l = tid + jj * 128;
        float acc = s_bc;
        #pragma unroll
        for (int k = 0; k < Kc; k++)
            acc += wc[k] * xp[l + k] + wc[Kc + k] * zp[l + k];
        g_cv[(size_t)t * Dc + l] = acc;
    }
}

// ---------------- K11: grouped expert linear: out = cv @ Wp[e] + bp[e] -------
__global__ __launch_bounds__(256) void k11_lin(const float* __restrict__ Wp,
                                               const float* __restrict__ bp,
                                               float* __restrict__ out) {
    int e = blockIdx.y;
    int c = blockIdx.x;
    int off0 = g_off[e], off1 = g_off[e + 1];
    int base = off0 + c * 64;
    if (base >= off1) return;

    __shared__ float sCv[64][33];
    __shared__ float sWp[32][96];
    __shared__ int   stok[64];
    __shared__ int   sval[64];
    int tid = threadIdx.x;
    if (tid < 64) {
        int s = base + tid;
        int v = (s < off1) ? 1 : 0;
        stok[tid] = v ? g_tok[s] : 0;
        sval[tid] = v;
    }
    __syncthreads();

    int rowg = tid >> 4, colg = tid & 15;  // 4 rows, 6 cols
    float acc[4][6] = {};
    for (int kk = 0; kk < Dc; kk += 32) {
        #pragma unroll
        for (int j = 0; j < 8; j++) {
            int id = tid + j * 256;
            int r = id >> 5, k = id & 31;
            sCv[r][k] = sval[r] ? g_cv[(size_t)stok[r] * Dc + kk + k] : 0.f;
        }
        #pragma unroll
        for (int j = 0; j < 12; j++) {
            int id = tid + j * 256;
            int kr = id / 96, cc = id - kr * 96;
            sWp[kr][cc] = Wp[(size_t)e * Dc * Pc + (size_t)(kk + kr) * Pc + cc];
        }
        __syncthreads();
        #pragma unroll
        for (int k = 0; k < 32; k++) {
            float a[4], w[6];
            #pragma unroll
            for (int i = 0; i < 4; i++) a[i] = sCv[rowg * 4 + i][k];
            #pragma unroll
            for (int j = 0; j < 6; j++) w[j] = sWp[k][colg * 6 + j];
            #pragma unroll
            for (int i = 0; i < 4; i++)
                #pragma unroll
                for (int j = 0; j < 6; j++) acc[i][j] += a[i] * w[j];
        }
        __syncthreads();
    }
    #pragma unroll
    for (int i = 0; i < 4; i++) {
        int r = rowg * 4 + i;
        if (sval[r]) {
            int tt = stok[r];
            #pragma unroll
            for (int j = 0; j < 6; j++)
                out[(size_t)tt * Pc + colg * 6 + j] = acc[i][j] + bp[e * Pc + colg * 6 + j];
        }
    }
}

// ---------------- launcher ---------------------------------------------------
extern "C" void kernel_launch(void* const* d_in, const int* in_sizes, int n_in,
                              void* d_out, int out_size) {
    const float* x      = (const float*)d_in[0];
    const float* router = (const float*)d_in[1];
    const float* Wq     = (const float*)d_in[2];
    const float* bq     = (const float*)d_in[3];
    const float* Wk     = (const float*)d_in[4];
    const float* bk     = (const float*)d_in[5];
    const float* Wv     = (const float*)d_in[6];
    const float* bv     = (const float*)d_in[7];
    const float* Wo     = (const float*)d_in[8];
    const float* bo     = (const float*)d_in[9];
    const float* Wc     = (const float*)d_in[10];
    const float* bc     = (const float*)d_in[11];
    const float* Wp     = (const float*)d_in[12];
    const float* bp     = (const float*)d_in[13];
    float* out = (float*)d_out;

    k1_qproj<<<Ec, 512>>>(router, Wq, bq);
    k2_qk<<<EHc, 256>>>(Wk, bk);
    k3_scores<<<BNc / 128, 256>>>(x);
    k4_softmax<<<Bc * EHc, 256>>>();
    k5_y<<<dim3(Dc / 128, Bc), 256>>>(x);
    k6_att<<<dim3(2, 4, Hc), 256>>>(Wv, bv);
    k7_oproj<<<dim3(8, 4), 256>>>(Wo, bo);
    k8_norm<<<Bc * Ec, 128>>>();
    k9_route<<<dim3(Nc / TOKS, Bc), 128>>>(x);
    kg1_count<<<64, 256>>>();
    kg2_scan<<<1, 512>>>();
    kg3_scatter<<<64, 256>>>();
    k10_conv<<<BNc, 128>>>(x, Wc, bc);
    k11_lin<<<dim3(BNc / 64, Ec), 256>>>(Wp, bp, out);
}

// round 6
// speedup vs baseline: 2.6781x; 1.3058x over previous
#include <cuda_runtime.h>
#include <math.h>

// Problem constants
#define Bc 32
#define Nc 512
#define Dc 512
#define Ec 8
#define Pc 96
#define Kc 25
#define Hc 4
#define DKc 128
#define PADc 12
#define BNc (Bc * Nc)   // 16384
#define EHc 32          // E*H

// ---------------- scratch (device globals) -----------------------------------
__device__ float g_qkT[Dc * EHc];            // Wk_h^T q_eh, [d][eh]
__device__ float g_qb[EHc];                  // q_eh . bk_h
__device__ float g_sc[(size_t)Bc * EHc * Nc];// scores -> softmax A [b][eh][n]
__device__ float g_y[(size_t)Bc * EHc * Dc]; // y = A @ X           [b][eh][d]
__device__ float g_att[Bc * Ec * Dc];        // y @ Wv + bv
__device__ float g_atto[Bc * Ec * Dc];       // att @ Wo + bo
__device__ int   g_idx[BNc];                 // chosen expert per token
__device__ float g_wx[(size_t)Ec * Dc * Pc]; // combined conv_x ∘ Wp   [e][d][p]
__device__ float g_zlin[Bc * Ec * Pc];       // z-branch + biases      [b*8+e][p]
__device__ int   g_blkcnt[64 * Ec];
__device__ int   g_blkoff[64 * Ec];
__device__ int   g_off[Ec + 1];
__device__ int   g_tok[BNc];                 // tokens grouped by expert

// ---------------- kA: fused q-projection + qk fold (per eh) ------------------
__global__ __launch_bounds__(256) void kA_qk(const float* __restrict__ router,
                                             const float* __restrict__ Wq,
                                             const float* __restrict__ bq,
                                             const float* __restrict__ Wk,
                                             const float* __restrict__ bk) {
    int eh = blockIdx.x;          // e*4 + h
    int e = eh >> 2, h = eh & 3;
    int tid = threadIdx.x, lane = tid & 31, warp = tid >> 5;
    __shared__ float sr[Dc];
    __shared__ float sq[DKc];
    __shared__ float red[256];

    sr[tid] = router[e * Dc + tid];
    sr[tid + 256] = router[e * Dc + 256 + tid];
    __syncthreads();

    // q slice: j in [0,128), split d-range over 2 thread halves
    int j = tid & 127, half = tid >> 7;
    float acc = 0.f;
    const float* wq = Wq + (size_t)(half * 256) * Dc + h * DKc + j;
    #pragma unroll 4
    for (int d = 0; d < 256; d++) acc += sr[half * 256 + d] * wq[(size_t)d * Dc];
    red[tid] = acc;
    __syncthreads();
    if (tid < DKc) sq[tid] = red[tid] + red[tid + 128] + bq[h * DKc + tid];
    __syncthreads();

    // qkT[d][eh] = Wk[d, head-slice] . q_slice
    for (int d = warp; d < Dc; d += 8) {
        const float* wr = Wk + (size_t)d * Dc + h * DKc;
        float p = 0.f;
        #pragma unroll
        for (int jj = 0; jj < 4; jj++) p += wr[lane + jj * 32] * sq[lane + jj * 32];
        #pragma unroll
        for (int o = 16; o > 0; o >>= 1) p += __shfl_down_sync(0xffffffffu, p, o);
        if (lane == 0) g_qkT[d * EHc + eh] = p;
    }
    // qb = q_slice . bk_slice
    red[tid] = (tid < DKc) ? sq[tid] * bk[h * DKc + tid] : 0.f;
    __syncthreads();
    for (int s = 128; s > 0; s >>= 1) { if (tid < s) red[tid] += red[tid + s]; __syncthreads(); }
    if (tid == 0) g_qb[eh] = red[0];
}

// ---------------- k3: scores = (X @ QK + qb) * scale -------------------------
__global__ __launch_bounds__(128) void k3_scores(const float* __restrict__ x) {
    __shared__ float sX[32][129];     // [k][tok]
    __shared__ float sQ[32][33];      // [k][eh]
    __shared__ float sQB[EHc];
    int t0 = blockIdx.x * 128;
    int b = t0 >> 9, n0 = t0 & 511;
    int tid = threadIdx.x;
    if (tid < EHc) sQB[tid] = g_qb[tid];
    int ty = tid >> 3, tx = tid & 7;  // 16 tok-groups x 8 eh-groups
    float acc[8][4] = {};
    for (int kk = 0; kk < Dc; kk += 32) {
        #pragma unroll
        for (int jj = 0; jj < 32; jj++) {
            int id = tid + jj * 128;
            int tok = id >> 5, k = id & 31;
            sX[k][tok] = x[(size_t)(t0 + tok) * Dc + kk + k];
        }
        #pragma unroll
        for (int jj = 0; jj < 8; jj++) {
            int id = tid + jj * 128;
            int k = id >> 5, ee = id & 31;
            sQ[k][ee] = g_qkT[(size_t)(kk + k) * EHc + ee];
        }
        __syncthreads();
        #pragma unroll
        for (int k = 0; k < 32; k++) {
            float q[4];
            #pragma unroll
            for (int jj = 0; jj < 4; jj++) q[jj] = sQ[k][tx * 4 + jj];
            #pragma unroll
            for (int i = 0; i < 8; i++) {
                float a = sX[k][ty * 8 + i];
                #pragma unroll
                for (int jj = 0; jj < 4; jj++) acc[i][jj] += a * q[jj];
            }
        }
        __syncthreads();
    }
    const float scale = 0.08838834764831845f;  // 1/sqrt(128)
    #pragma unroll
    for (int i = 0; i < 8; i++) {
        int n = n0 + ty * 8 + i;
        #pragma unroll
        for (int jj = 0; jj < 4; jj++) {
            int ee = tx * 4 + jj;
            g_sc[((size_t)b * EHc + ee) * Nc + n] = (acc[i][jj] + sQB[ee]) * scale;
        }
    }
}

// ---------------- k4: softmax over n per (b,eh) ------------------------------
__global__ __launch_bounds__(256) void k4_softmax() {
    int row = blockIdx.x;
    int tid = threadIdx.x;
    __shared__ float red[256];
    float v0 = g_sc[(size_t)row * Nc + tid];
    float v1 = g_sc[(size_t)row * Nc + 256 + tid];
    red[tid] = fmaxf(v0, v1);
    __syncthreads();
    for (int s = 128; s > 0; s >>= 1) { if (tid < s) red[tid] = fmaxf(red[tid], red[tid + s]); __syncthreads(); }
    float M = red[0];
    __syncthreads();
    float e0 = expf(v0 - M), e1 = expf(v1 - M);
    red[tid] = e0 + e1;
    __syncthreads();
    for (int s = 128; s > 0; s >>= 1) { if (tid < s) red[tid] += red[tid + s]; __syncthreads(); }
    float inv = 1.0f / red[0];
    g_sc[(size_t)row * Nc + tid] = e0 * inv;
    g_sc[(size_t)row * Nc + 256 + tid] = e1 * inv;
}

// ---------------- k5: y[b][eh][d] = sum_n A[b][eh][n] X[b][n][d] -------------
__global__ __launch_bounds__(128) void k5_y(const float* __restrict__ x) {
    __shared__ float sA[32][33];      // [eh][n]
    __shared__ float sX[32][128];     // [n][d]
    int d0 = blockIdx.x * 128;
    int b = blockIdx.y;
    int tid = threadIdx.x;
    int ty = tid >> 4, tx = tid & 15;  // 8 eh-groups x 16 d-lanes
    float acc[4][8] = {};
    for (int kk = 0; kk < Nc; kk += 32) {
        #pragma unroll
        for (int jj = 0; jj < 8; jj++) {
            int id = tid + jj * 128;
            int ee = id >> 5, n = id & 31;
            sA[ee][n] = g_sc[((size_t)b * EHc + ee) * Nc + kk + n];
        }
        #pragma unroll
        for (int jj = 0; jj < 32; jj++) {
            int id = tid + jj * 128;
            int n = id >> 7, d = id & 127;
            sX[n][d] = x[((size_t)b * Nc + kk + n) * Dc + d0 + d];
        }
        __syncthreads();
        #pragma unroll
        for (int n = 0; n < 32; n++) {
            float xv[8];
            #pragma unroll
            for (int i = 0; i < 8; i++) xv[i] = sX[n][tx + i * 16];  // conflict-free
            #pragma unroll
            for (int r = 0; r < 4; r++) {
                float a = sA[ty * 4 + r][n];
                #pragma unroll
                for (int i = 0; i < 8; i++) acc[r][i] += a * xv[i];
            }
        }
        __syncthreads();
    }
    #pragma unroll
    for (int r = 0; r < 4; r++)
        #pragma unroll
        for (int i = 0; i < 8; i++)
            g_y[((size_t)b * EHc + ty * 4 + r) * Dc + d0 + tx + i * 16] = acc[r][i];
}

// ---------------- k6: att = y @ Wv(head block) + bv  (32x32 tiles) -----------
__global__ __launch_bounds__(128) void k6_att(const float* __restrict__ Wv,
                                              const float* __restrict__ bv) {
    int c0 = blockIdx.x * 32;          // col block; h = c0/128
    int r0 = blockIdx.y * 32;          // rows: b*8+e
    int h = c0 >> 7;
    __shared__ float sY[32][33];
    __shared__ float sW[32][33];
    int tid = threadIdx.x;
    int ty = tid >> 4, tx = tid & 15;  // 8 row-groups x 16 col-lanes
    float acc[4][2] = {};
    for (int kk = 0; kk < Dc; kk += 32) {
        #pragma unroll
        for (int jj = 0; jj < 8; jj++) {
            int id = tid + jj * 128;
            int r = id >> 5, k = id & 31;
            sY[r][k] = g_y[((size_t)(r0 + r) * 4 + h) * Dc + kk + k];
        }
        #pragma unroll
        for (int jj = 0; jj < 8; jj++) {
            int id = tid + jj * 128;
            int k = id >> 5, c = id & 31;
            sW[k][c] = Wv[(size_t)(kk + k) * Dc + c0 + c];
        }
        __syncthreads();
        #pragma unroll
        for (int k = 0; k < 32; k++) {
            float w0 = sW[k][tx], w1 = sW[k][tx + 16];
            #pragma unroll
            for (int i = 0; i < 4; i++) {
                float a = sY[ty * 4 + i][k];
                acc[i][0] += a * w0;
                acc[i][1] += a * w1;
            }
        }
        __syncthreads();
    }
    #pragma unroll
    for (int i = 0; i < 4; i++) {
        int row = r0 + ty * 4 + i;
        g_att[(size_t)row * Dc + c0 + tx]      = acc[i][0] + bv[c0 + tx];
        g_att[(size_t)row * Dc + c0 + tx + 16] = acc[i][1] + bv[c0 + tx + 16];
    }
}

// ---------------- k7: atto = att @ Wo + bo  (32x32 tiles) --------------------
__global__ __launch_bounds__(128) void k7_oproj(const float* __restrict__ Wo,
                                                const float* __restrict__ bo) {
    int c0 = blockIdx.x * 32;
    int r0 = blockIdx.y * 32;
    __shared__ float sA[32][33];
    __shared__ float sW[32][33];
    int tid = threadIdx.x;
    int ty = tid >> 4, tx = tid & 15;
    float acc[4][2] = {};
    for (int kk = 0; kk < Dc; kk += 32) {
        #pragma unroll
        for (int jj = 0; jj < 8; jj++) {
            int id = tid + jj * 128;
            int r = id >> 5, k = id & 31;
            sA[r][k] = g_att[(size_t)(r0 + r) * Dc + kk + k];
        }
        #pragma unroll
        for (int jj = 0; jj < 8; jj++) {
            int id = tid + jj * 128;
            int k = id >> 5, c = id & 31;
            sW[k][c] = Wo[(size_t)(kk + k) * Dc + c0 + c];
        }
        __syncthreads();
        #pragma unroll
        for (int k = 0; k < 32; k++) {
            float w0 = sW[k][tx], w1 = sW[k][tx + 16];
            #pragma unroll
            for (int i = 0; i < 4; i++) {
                float a = sA[ty * 4 + i][k];
                acc[i][0] += a * w0;
                acc[i][1] += a * w1;
            }
        }
        __syncthreads();
    }
    #pragma unroll
    for (int i = 0; i < 4; i++) {
        int row = r0 + ty * 4 + i;
        g_atto[(size_t)row * Dc + c0 + tx]      = acc[i][0] + bo[c0 + tx];
        g_atto[(size_t)row * Dc + c0 + tx + 16] = acc[i][1] + bo[c0 + tx + 16];
    }
}

// ---------------- k9: routing argmax (norm_x cancels; norms fused) -----------
#define TOKS 16
__global__ __launch_bounds__(128) void k9_route(const float* __restrict__ x) {
    int b = blockIdx.y;
    int n0 = blockIdx.x * TOKS;
    int tid = threadIdx.x;
    __shared__ float s_att[Ec][516];
    __shared__ float s_norm[Ec];
    __shared__ float s_dot[TOKS][Ec + 1];

    for (int i = tid; i < Ec * Dc; i += 128) {
        int e = i >> 9, d = i & 511;
        s_att[e][d] = g_atto[(b * Ec + e) * Dc + d];
    }
    __syncthreads();

    // norms (fused): 16 threads per expert, shfl reduce within 16-lane groups
    {
        int e = tid >> 4, seg = tid & 15;
        float ps = 0.f;
        #pragma unroll
        for (int d = 0; d < 32; d++) {
            float v = s_att[e][seg * 32 + d];
            ps += v * v;
        }
        #pragma unroll
        for (int o = 8; o > 0; o >>= 1) ps += __shfl_down_sync(0xffffffffu, ps, o, 16);
        if (seg == 0) s_norm[e] = sqrtf(ps);
    }
    __syncthreads();

    int tok = tid >> 3, e = tid & 7;
    const float* xr = x + ((size_t)b * Nc + n0 + tok) * Dc;
    const float* ar = s_att[e];
    float c0 = 0, c1 = 0, c2 = 0, c3 = 0;
    for (int d = 0; d < Dc; d += 4) {
        c0 += xr[d + 0] * ar[d + 0];
        c1 += xr[d + 1] * ar[d + 1];
        c2 += xr[d + 2] * ar[d + 2];
        c3 += xr[d + 3] * ar[d + 3];
    }
    s_dot[tok][e] = (c0 + c1) + (c2 + c3);
    __syncthreads();

    if (tid < TOKS) {
        float best = -INFINITY; int bi = 0;
        #pragma unroll
        for (int ee = 0; ee < Ec; ee++) {
            float v = s_dot[tid][ee] / s_norm[ee];
            if (v > best) { best = v; bi = ee; }   // first-max, matches jnp.argmax
        }
        g_idx[b * Nc + n0 + tid] = bi;
    }
}

// ---------------- KG: expert grouping ----------------------------------------
__global__ __launch_bounds__(256) void kg1_count() {
    __shared__ int cnt[Ec];
    int j = blockIdx.x, tid = threadIdx.x;
    if (tid < Ec) cnt[tid] = 0;
    __syncthreads();
    atomicAdd(&cnt[g_idx[j * 256 + tid]], 1);
    __syncthreads();
    if (tid < Ec) g_blkcnt[j * Ec + tid] = cnt[tid];
}

__global__ __launch_bounds__(512) void kg2_scan() {
    __shared__ int stot[Ec];
    __shared__ int soff[Ec];
    int tid = threadIdx.x;
    if (tid < Ec) {
        int run = 0;
        for (int j = 0; j < 64; j++) {
            int c = g_blkcnt[j * Ec + tid];
            g_blkoff[j * Ec + tid] = run;
            run += c;
        }
        stot[tid] = run;
    }
    __syncthreads();
    if (tid == 0) {
        int acc = 0;
        for (int e = 0; e < Ec; e++) { soff[e] = acc; g_off[e] = acc; acc += stot[e]; }
        g_off[Ec] = acc;
    }
    __syncthreads();
    g_blkoff[tid] += soff[tid & 7];
}

__global__ __launch_bounds__(256) void kg3_scatter() {
    __shared__ int cnt[Ec];
    int j = blockIdx.x, tid = threadIdx.x;
    if (tid < Ec) cnt[tid] = 0;
    __syncthreads();
    int t = j * 256 + tid;
    int e = g_idx[t];
    int p = atomicAdd(&cnt[e], 1);
    g_tok[g_blkoff[j * Ec + e] + p] = t;
}

// ---------------- kP1: fold conv_x into Wp: Wxe[e][m][p] ---------------------
__global__ __launch_bounds__(128) void kP1_fold(const float* __restrict__ Wc,
                                                const float* __restrict__ Wp) {
    int e = blockIdx.x;
    int m0 = blockIdx.y * 32;
    int tid = threadIdx.x;
    __shared__ float sWp[56][Pc];   // rows l = m0-12 .. m0+43
    __shared__ float swc[Kc];
    for (int id = tid; id < 56 * Pc; id += 128) {
        int lr = id / Pc, p = id - lr * Pc;
        int l = m0 - 12 + lr;
        sWp[lr][p] = (l >= 0 && l < Dc) ? Wp[(size_t)e * Dc * Pc + (size_t)l * Pc + p] : 0.f;
    }
    if (tid < Kc) swc[tid] = Wc[e * 2 * Kc + tid];   // x-channel weights
    __syncthreads();
    if (tid < Pc) {
        #pragma unroll 2
        for (int m = 0; m < 32; m++) {
            float acc = 0.f;
            #pragma unroll
            for (int k = 0; k < Kc; k++) acc += swc[k] * sWp[m + 24 - k][tid];
            g_wx[(size_t)e * Dc * Pc + (size_t)(m0 + m) * Pc + tid] = acc;
        }
    }
}

// ---------------- kP2: z-branch per (b,e): zlin = (conv_z(z)+bc)@Wp + bp -----
__global__ __launch_bounds__(128) void kP2_z(const float* __restrict__ Wc,
                                             const float* __restrict__ bc,
                                             const float* __restrict__ Wp,
                                             const float* __restrict__ bp) {
    int r = blockIdx.x;      // b*8+e
    int e = r & 7;
    int tid = threadIdx.x;
    __shared__ float zp[Dc + 2 * PADc];
    __shared__ float cz[Dc];
    __shared__ float swz[Kc];
    __shared__ float s_bc;

    const float* zr = g_atto + (size_t)r * Dc;
    for (int i = tid; i < Dc + 2 * PADc; i += 128) {
        bool in = (i >= PADc) && (i < Dc + PADc);
        zp[i] = in ? zr[i - PADc] : 0.f;
    }
    if (tid < Kc) swz[tid] = Wc[e * 2 * Kc + Kc + tid];
    if (tid == 0) s_bc = bc[e];
    __syncthreads();
    #pragma unroll
    for (int jj = 0; jj < 4; jj++) {
        int l = tid * 4 + jj;
        if (l < Dc) {
            float acc = s_bc;
            #pragma unroll
            for (int k = 0; k < Kc; k++) acc += swz[k] * zp[l + k];
            cz[l] = acc;
        }
    }
    __syncthreads();
    if (tid < Pc) {
        const float* wp = Wp + (size_t)e * Dc * Pc + tid;
        float a0 = bp[e * Pc + tid], a1 = 0, a2 = 0, a3 = 0;
        for (int l = 0; l < Dc; l += 4) {
            a0 += cz[l + 0] * wp[(size_t)(l + 0) * Pc];
            a1 += cz[l + 1] * wp[(size_t)(l + 1) * Pc];
            a2 += cz[l + 2] * wp[(size_t)(l + 2) * Pc];
            a3 += cz[l + 3] * wp[(size_t)(l + 3) * Pc];
        }
        g_zlin[r * Pc + tid] = (a0 + a1) + (a2 + a3);
    }
}

// ---------------- k11: grouped GEMM  out = x @ Wxe[e] + zlin -----------------
__global__ __launch_bounds__(128) void k11_lin(const float* __restrict__ x,
                                               float* __restrict__ out) {
    int e = blockIdx.y;
    int c = blockIdx.x;
    int off0 = g_off[e], off1 = g_off[e + 1];
    int base = off0 + c * 64;
    if (base >= off1) return;

    __shared__ float sX[64][33];     // [tok][k]
    __shared__ float sW[32][Pc];     // [k][p]
    __shared__ int   stok[64];
    __shared__ int   sval[64];
    int tid = threadIdx.x;
    if (tid < 64) {
        int s = base + tid;
        int v = (s < off1) ? 1 : 0;
        stok[tid] = v ? g_tok[s] : 0;
        sval[tid] = v;
    }
    __syncthreads();

    int ty = tid >> 4, tx = tid & 15;  // 8 tok-groups x 16 p-lanes(6 each)
    float acc[8][6] = {};
    const float* wbase = g_wx + (size_t)e * Dc * Pc;
    for (int kk = 0; kk < Dc; kk += 32) {
        #pragma unroll
        for (int jj = 0; jj < 16; jj++) {
            int id = tid + jj * 128;
            int rr = id >> 5, k = id & 31;
            sX[rr][k] = sval[rr] ? x[(size_t)stok[rr] * Dc + kk + k] : 0.f;
        }
        #pragma unroll
        for (int jj = 0; jj < 24; jj++) {
            int id = tid + jj * 128;
            int k = id / Pc, p = id - k * Pc;
            sW[k][p] = wbase[(size_t)(kk + k) * Pc + p];
        }
        __syncthreads();
        #pragma unroll
        for (int k = 0; k < 32; k++) {
            float w[6];
            #pragma unroll
            for (int jj = 0; jj < 6; jj++) w[jj] = sW[k][tx * 6 + jj];
            #pragma unroll
            for (int i = 0; i < 8; i++) {
                float a = sX[ty * 8 + i][k];
                #pragma unroll
                for (int jj = 0; jj < 6; jj++) acc[i][jj] += a * w[jj];
            }
        }
        __syncthreads();
    }
    #pragma unroll
    for (int i = 0; i < 8; i++) {
        int rr = ty * 8 + i;
        if (sval[rr]) {
            int tt = stok[rr];
            int zb = ((tt >> 9) * Ec + e) * Pc;
            #pragma unroll
            for (int jj = 0; jj < 6; jj++)
                out[(size_t)tt * Pc + tx * 6 + jj] = acc[i][jj] + g_zlin[zb + tx * 6 + jj];
        }
    }
}

// ---------------- launcher ---------------------------------------------------
extern "C" void kernel_launch(void* const* d_in, const int* in_sizes, int n_in,
                              void* d_out, int out_size) {
    const float* x      = (const float*)d_in[0];
    const float* router = (const float*)d_in[1];
    const float* Wq     = (const float*)d_in[2];
    const float* bq     = (const float*)d_in[3];
    const float* Wk     = (const float*)d_in[4];
    const float* bk     = (const float*)d_in[5];
    const float* Wv     = (const float*)d_in[6];
    const float* bv     = (const float*)d_in[7];
    const float* Wo     = (const float*)d_in[8];
    const float* bo     = (const float*)d_in[9];
    const float* Wc     = (const float*)d_in[10];
    const float* bc     = (const float*)d_in[11];
    const float* Wp     = (const float*)d_in[12];
    const float* bp     = (const float*)d_in[13];
    float* out = (float*)d_out;

    kP1_fold<<<dim3(Ec, 16), 128>>>(Wc, Wp);        // weight-only, early
    kA_qk<<<EHc, 256>>>(router, Wq, bq, Wk, bk);
    k3_scores<<<BNc / 128, 128>>>(x);
    k4_softmax<<<Bc * EHc, 256>>>();
    k5_y<<<dim3(Dc / 128, Bc), 128>>>(x);
    k6_att<<<dim3(16, 8), 128>>>(Wv, bv);
    k7_oproj<<<dim3(16, 8), 128>>>(Wo, bo);
    k9_route<<<dim3(Nc / TOKS, Bc), 128>>>(x);
    kg1_count<<<64, 256>>>();
    kg2_scan<<<1, 512>>>();
    kg3_scatter<<<64, 256>>>();
    kP2_z<<<Bc * Ec, 128>>>(Wc, bc, Wp, bp);
    k11_lin<<<dim3(BNc / 64, Ec), 128>>>(x, out);
}

// round 8
// speedup vs baseline: 3.6285x; 1.3549x over previous
#include <cuda_runtime.h>
#include <math.h>

// Problem constants
#define Bc 32
#define Nc 512
#define Dc 512
#define Ec 8
#define Pc 96
#define Kc 25
#define Hc 4
#define DKc 128
#define PADc 12
#define BNc (Bc * Nc)   // 16384
#define EHc 32          // E*H

// ---------------- scratch (device globals) -----------------------------------
__device__ __align__(16) float g_qkT[Dc * EHc];            // [d][eh]
__device__ float g_qb[EHc];
__device__ __align__(16) float g_sc[(size_t)Bc * EHc * Nc];// [b][eh][n]
__device__ __align__(16) float g_y[(size_t)Bc * EHc * Dc]; // [b][eh][d]
__device__ __align__(16) float g_att[Bc * Ec * Dc];
__device__ __align__(16) float g_atto[Bc * Ec * Dc];
__device__ int   g_idx[BNc];
__device__ __align__(16) float g_wx[(size_t)Ec * Dc * Pc]; // [e][d][p]
__device__ float g_zlin[Bc * Ec * Pc];
__device__ int   g_blkcnt[256 * Ec];     // per 64-token block
__device__ int   g_blkoff[256 * Ec];
__device__ int   g_off[Ec + 1];
__device__ int   g_tok[BNc];

// ---------------- kA: fused q-projection + qk fold (per eh) ------------------
__global__ __launch_bounds__(256) void kA_qk(const float* __restrict__ router,
                                             const float* __restrict__ Wq,
                                             const float* __restrict__ bq,
                                             const float* __restrict__ Wk,
                                             const float* __restrict__ bk) {
    int eh = blockIdx.x;
    int e = eh >> 2, h = eh & 3;
    int tid = threadIdx.x, lane = tid & 31, warp = tid >> 5;
    __shared__ float sr[Dc];
    __shared__ float sq[DKc];
    __shared__ float red[256];

    sr[tid] = router[e * Dc + tid];
    sr[tid + 256] = router[e * Dc + 256 + tid];
    __syncthreads();

    int j = tid & 127, half = tid >> 7;
    float acc = 0.f;
    const float* wq = Wq + (size_t)(half * 256) * Dc + h * DKc + j;
    #pragma unroll 4
    for (int d = 0; d < 256; d++) acc += sr[half * 256 + d] * wq[(size_t)d * Dc];
    red[tid] = acc;
    __syncthreads();
    if (tid < DKc) sq[tid] = red[tid] + red[tid + 128] + bq[h * DKc + tid];
    __syncthreads();

    for (int d = warp; d < Dc; d += 8) {
        const float* wr = Wk + (size_t)d * Dc + h * DKc;
        float p = 0.f;
        #pragma unroll
        for (int jj = 0; jj < 4; jj++) p += wr[lane + jj * 32] * sq[lane + jj * 32];
        #pragma unroll
        for (int o = 16; o > 0; o >>= 1) p += __shfl_down_sync(0xffffffffu, p, o);
        if (lane == 0) g_qkT[d * EHc + eh] = p;
    }
    red[tid] = (tid < DKc) ? sq[tid] * bk[h * DKc + tid] : 0.f;
    __syncthreads();
    for (int s = 128; s > 0; s >>= 1) { if (tid < s) red[tid] += red[tid + s]; __syncthreads(); }
    if (tid == 0) g_qb[eh] = red[0];
}

// ---------------- k3: scores = (X @ QK + qb) * scale  (64-token blocks) ------
__global__ __launch_bounds__(128) void k3_scores(const float* __restrict__ x) {
    __shared__ float sX[32][65];     // [k][tok]  transposed
    __shared__ float sQ[32][33];     // [k][eh]
    __shared__ float sQB[EHc];
    int t0 = blockIdx.x * 64;
    int b = t0 >> 9, n0 = t0 & 511;
    int tid = threadIdx.x;
    if (tid < EHc) sQB[tid] = g_qb[tid];
    int ty = tid >> 3, tx = tid & 7;  // 16 tok-groups(4) x 8 eh-groups(4)
    float acc[4][4] = {};
    const float4* x4 = (const float4*)x;
    const float4* q4 = (const float4*)g_qkT;
    for (int kk = 0; kk < Dc; kk += 32) {
        // x: 64 tok x 32 k -> transposed into sX; float4 loads
        #pragma unroll
        for (int jj = 0; jj < 4; jj++) {
            int id = tid + jj * 128;          // 512 float4
            int tok = id >> 3, c4 = id & 7;
            float4 v = x4[((size_t)(t0 + tok) * Dc + kk) / 4 + c4];
            sX[c4 * 4 + 0][tok] = v.x;
            sX[c4 * 4 + 1][tok] = v.y;
            sX[c4 * 4 + 2][tok] = v.z;
            sX[c4 * 4 + 3][tok] = v.w;
        }
        // qkT: 32 k x 32 eh
        #pragma unroll
        for (int jj = 0; jj < 2; jj++) {
            int id = tid + jj * 128;          // 256 float4
            int k = id >> 3, e4 = id & 7;
            float4 v = q4[((size_t)(kk + k) * EHc) / 4 + e4];
            sQ[k][e4 * 4 + 0] = v.x;
            sQ[k][e4 * 4 + 1] = v.y;
            sQ[k][e4 * 4 + 2] = v.z;
            sQ[k][e4 * 4 + 3] = v.w;
        }
        __syncthreads();
        #pragma unroll
        for (int k = 0; k < 32; k++) {
            float q[4], a[4];
            #pragma unroll
            for (int jj = 0; jj < 4; jj++) q[jj] = sQ[k][tx * 4 + jj];
            #pragma unroll
            for (int i = 0; i < 4; i++) a[i] = sX[k][ty * 4 + i];
            #pragma unroll
            for (int i = 0; i < 4; i++)
                #pragma unroll
                for (int jj = 0; jj < 4; jj++) acc[i][jj] += a[i] * q[jj];
        }
        __syncthreads();
    }
    const float scale = 0.08838834764831845f;
    #pragma unroll
    for (int i = 0; i < 4; i++) {
        int n = n0 + ty * 4 + i;
        #pragma unroll
        for (int jj = 0; jj < 4; jj++) {
            int ee = tx * 4 + jj;
            g_sc[((size_t)b * EHc + ee) * Nc + n] = (acc[i][jj] + sQB[ee]) * scale;
        }
    }
}

// ---------------- k4: softmax over n per (b,eh) ------------------------------
__global__ __launch_bounds__(256) void k4_softmax() {
    int row = blockIdx.x;
    int tid = threadIdx.x;
    __shared__ float red[256];
    float v0 = g_sc[(size_t)row * Nc + tid];
    float v1 = g_sc[(size_t)row * Nc + 256 + tid];
    red[tid] = fmaxf(v0, v1);
    __syncthreads();
    for (int s = 128; s > 0; s >>= 1) { if (tid < s) red[tid] = fmaxf(red[tid], red[tid + s]); __syncthreads(); }
    float M = red[0];
    __syncthreads();
    float e0 = expf(v0 - M), e1 = expf(v1 - M);
    red[tid] = e0 + e1;
    __syncthreads();
    for (int s = 128; s > 0; s >>= 1) { if (tid < s) red[tid] += red[tid + s]; __syncthreads(); }
    float inv = 1.0f / red[0];
    g_sc[(size_t)row * Nc + tid] = e0 * inv;
    g_sc[(size_t)row * Nc + 256 + tid] = e1 * inv;
}

// ---------------- k5: y[b][eh][d-block64] = A @ X ----------------------------
__global__ __launch_bounds__(128) void k5_y(const float* __restrict__ x) {
    __shared__ float sA[32][33];      // [eh][n]
    __shared__ float sX[32][64];      // [n][d]
    int d0 = blockIdx.x * 64;
    int b = blockIdx.y;
    int tid = threadIdx.x;
    int ty = tid >> 4, tx = tid & 15;  // 8 eh-groups(4) x 16 d-lanes(4, stride16)
    float acc[4][4] = {};
    const float4* x4 = (const float4*)x;
    const float4* s4 = (const float4*)g_sc;
    float4* sX4 = (float4*)sX;
    for (int kk = 0; kk < Nc; kk += 32) {
        #pragma unroll
        for (int jj = 0; jj < 2; jj++) {
            int id = tid + jj * 128;           // 256 float4 (A: 32eh x 32n)
            int ee = id >> 3, n4 = id & 7;
            float4 v = s4[(((size_t)b * EHc + ee) * Nc + kk) / 4 + n4];
            sA[ee][n4 * 4 + 0] = v.x;
            sA[ee][n4 * 4 + 1] = v.y;
            sA[ee][n4 * 4 + 2] = v.z;
            sA[ee][n4 * 4 + 3] = v.w;
        }
        #pragma unroll
        for (int jj = 0; jj < 4; jj++) {
            int id = tid + jj * 128;           // 512 float4 (X: 32n x 64d)
            int n = id >> 4, d4 = id & 15;
            sX4[n * 16 + d4] = x4[(((size_t)b * Nc + kk + n) * Dc + d0) / 4 + d4];
        }
        __syncthreads();
        #pragma unroll
        for (int n = 0; n < 32; n++) {
            float xv[4], a[4];
            #pragma unroll
            for (int i = 0; i < 4; i++) xv[i] = sX[n][tx + i * 16];
            #pragma unroll
            for (int r = 0; r < 4; r++) a[r] = sA[ty * 4 + r][n];
            #pragma unroll
            for (int r = 0; r < 4; r++)
                #pragma unroll
                for (int i = 0; i < 4; i++) acc[r][i] += a[r] * xv[i];
        }
        __syncthreads();
    }
    #pragma unroll
    for (int r = 0; r < 4; r++)
        #pragma unroll
        for (int i = 0; i < 4; i++)
            g_y[((size_t)b * EHc + ty * 4 + r) * Dc + d0 + tx + i * 16] = acc[r][i];
}

// ---------------- k6: att = y @ Wv(head block) + bv --------------------------
__global__ __launch_bounds__(128) void k6_att(const float* __restrict__ Wv,
                                              const float* __restrict__ bv) {
    int c0 = blockIdx.x * 32;
    int r0 = blockIdx.y * 32;
    int h = c0 >> 7;
    __shared__ float sY[32][33];
    __shared__ float sW[32][33];
    int tid = threadIdx.x;
    int ty = tid >> 4, tx = tid & 15;
    float acc[4][2] = {};
    for (int kk = 0; kk < Dc; kk += 32) {
        #pragma unroll
        for (int jj = 0; jj < 8; jj++) {
            int id = tid + jj * 128;
            int r = id >> 5, k = id & 31;
            sY[r][k] = g_y[((size_t)(r0 + r) * 4 + h) * Dc + kk + k];
        }
        #pragma unroll
        for (int jj = 0; jj < 8; jj++) {
            int id = tid + jj * 128;
            int k = id >> 5, c = id & 31;
            sW[k][c] = Wv[(size_t)(kk + k) * Dc + c0 + c];
        }
        __syncthreads();
        #pragma unroll
        for (int k = 0; k < 32; k++) {
            float w0 = sW[k][tx], w1 = sW[k][tx + 16];
            #pragma unroll
            for (int i = 0; i < 4; i++) {
                float a = sY[ty * 4 + i][k];
                acc[i][0] += a * w0;
                acc[i][1] += a * w1;
            }
        }
        __syncthreads();
    }
    #pragma unroll
    for (int i = 0; i < 4; i++) {
        int row = r0 + ty * 4 + i;
        g_att[(size_t)row * Dc + c0 + tx]      = acc[i][0] + bv[c0 + tx];
        g_att[(size_t)row * Dc + c0 + tx + 16] = acc[i][1] + bv[c0 + tx + 16];
    }
}

// ---------------- k7: atto = att @ Wo + bo -----------------------------------
__global__ __launch_bounds__(128) void k7_oproj(const float* __restrict__ Wo,
                                                const float* __restrict__ bo) {
    int c0 = blockIdx.x * 32;
    int r0 = blockIdx.y * 32;
    __shared__ float sA[32][33];
    __shared__ float sW[32][33];
    int tid = threadIdx.x;
    int ty = tid >> 4, tx = tid & 15;
    float acc[4][2] = {};
    for (int kk = 0; kk < Dc; kk += 32) {
        #pragma unroll
        for (int jj = 0; jj < 8; jj++) {
            int id = tid + jj * 128;
            int r = id >> 5, k = id & 31;
            sA[r][k] = g_att[(size_t)(r0 + r) * Dc + kk + k];
        }
        #pragma unroll
        for (int jj = 0; jj < 8; jj++) {
            int id = tid + jj * 128;
            int k = id >> 5, c = id & 31;
            sW[k][c] = Wo[(size_t)(kk + k) * Dc + c0 + c];
        }
        __syncthreads();
        #pragma unroll
        for (int k = 0; k < 32; k++) {
            float w0 = sW[k][tx], w1 = sW[k][tx + 16];
            #pragma unroll
            for (int i = 0; i < 4; i++) {
                float a = sA[ty * 4 + i][k];
                acc[i][0] += a * w0;
                acc[i][1] += a * w1;
            }
        }
        __syncthreads();
    }
    #pragma unroll
    for (int i = 0; i < 4; i++) {
        int row = r0 + ty * 4 + i;
        g_atto[(size_t)row * Dc + c0 + tx]      = acc[i][0] + bo[c0 + tx];
        g_atto[(size_t)row * Dc + c0 + tx + 16] = acc[i][1] + bo[c0 + tx + 16];
    }
}

// ---------------- k9: routing argmax + per-block expert counts ---------------
// Thread-per-token, 8 expert accumulators in registers; att broadcast from smem
__global__ __launch_bounds__(64) void k9_route(const float* __restrict__ x) {
    int b = blockIdx.y;
    int n0 = blockIdx.x * 64;
    int tid = threadIdx.x;
    __shared__ float4 s_att4[Ec][DKc];   // [e][d/4], 16KB
    __shared__ float  s_red[Ec][8];
    __shared__ float  s_norm[Ec];
    __shared__ int    s_cnt[Ec];

    const float4* a4 = (const float4*)(g_atto + (size_t)b * Ec * Dc);
    for (int i = tid; i < Ec * DKc; i += 64)
        s_att4[i >> 7][i & 127] = a4[i];
    if (tid < Ec) s_cnt[tid] = 0;
    __syncthreads();

    // norms: 8 threads per expert, 64-float segments
    {
        int e = tid >> 3, seg = tid & 7;
        float ps = 0.f;
        #pragma unroll
        for (int q = 0; q < 16; q++) {
            float4 v = s_att4[e][seg * 16 + q];
            ps += v.x * v.x + v.y * v.y + v.z * v.z + v.w * v.w;
        }
        s_red[e][seg] = ps;
    }
    __syncthreads();
    if (tid < Ec) {
        float s = 0.f;
        #pragma unroll
        for (int q = 0; q < 8; q++) s += s_red[tid][q];
        s_norm[tid] = sqrtf(s);
    }
    __syncthreads();

    int t = b * Nc + n0 + tid;
    const float4* xr4 = (const float4*)(x + (size_t)t * Dc);
    float acc[Ec] = {};
    #pragma unroll 4
    for (int d4 = 0; d4 < DKc; d4++) {
        float4 xv = xr4[d4];
        #pragma unroll
        for (int e = 0; e < Ec; e++) {
            float4 av = s_att4[e][d4];
            acc[e] += xv.x * av.x + xv.y * av.y + xv.z * av.z + xv.w * av.w;
        }
    }
    float best = -INFINITY; int bi = 0;
    #pragma unroll
    for (int e = 0; e < Ec; e++) {
        float v = acc[e] / s_norm[e];
        if (v > best) { best = v; bi = e; }   // first-max, matches jnp.argmax
    }
    g_idx[t] = bi;
    atomicAdd(&s_cnt[bi], 1);
    __syncthreads();
    if (tid < Ec) g_blkcnt[(b * 8 + blockIdx.x) * Ec + tid] = s_cnt[tid];
}

// ---------------- kg2: scan 256x8 block counts -> offsets --------------------
__global__ __launch_bounds__(256) void kg2_scan() {
    __shared__ int s_cnt[256 * Ec];
    __shared__ int stot[Ec];
    __shared__ int soff[Ec];
    int tid = threadIdx.x;
    #pragma unroll
    for (int e = 0; e < Ec; e++) s_cnt[tid * Ec + e] = g_blkcnt[tid * Ec + e];
    __syncthreads();
    if (tid < Ec) {
        int run = 0;
        for (int blk = 0; blk < 256; blk++) {
            g_blkoff[blk * Ec + tid] = run;
            run += s_cnt[blk * Ec + tid];
        }
        stot[tid] = run;
    }
    __syncthreads();
    if (tid == 0) {
        int acc = 0;
        for (int e = 0; e < Ec; e++) { soff[e] = acc; g_off[e] = acc; acc += stot[e]; }
        g_off[Ec] = acc;
    }
    __syncthreads();
    #pragma unroll
    for (int e = 0; e < Ec; e++) g_blkoff[tid * Ec + e] += soff[e];
}

// ---------------- kg3: scatter tokens grouped by expert ----------------------
__global__ __launch_bounds__(64) void kg3_scatter() {
    __shared__ int cnt[Ec];
    int blk = blockIdx.x, tid = threadIdx.x;
    if (tid < Ec) cnt[tid] = 0;
    __syncthreads();
    int t = blk * 64 + tid;
    int e = g_idx[t];
    int p = atomicAdd(&cnt[e], 1);
    g_tok[g_blkoff[blk * Ec + e] + p] = t;
}

// ---------------- kP1: fold conv_x into Wp -----------------------------------
__global__ __launch_bounds__(128) void kP1_fold(const float* __restrict__ Wc,
                                                const float* __restrict__ Wp) {
    int e = blockIdx.x;
    int m0 = blockIdx.y * 32;
    int tid = threadIdx.x;
    __shared__ float sWp[56][Pc];
    __shared__ float swc[Kc];
    for (int id = tid; id < 56 * Pc; id += 128) {
        int lr = id / Pc, p = id - lr * Pc;
        int l = m0 - 12 + lr;
        sWp[lr][p] = (l >= 0 && l < Dc) ? Wp[(size_t)e * Dc * Pc + (size_t)l * Pc + p] : 0.f;
    }
    if (tid < Kc) swc[tid] = Wc[e * 2 * Kc + tid];
    __syncthreads();
    if (tid < Pc) {
        #pragma unroll 2
        for (int m = 0; m < 32; m++) {
            float acc = 0.f;
            #pragma unroll
            for (int k = 0; k < Kc; k++) acc += swc[k] * sWp[m + 24 - k][tid];
            g_wx[(size_t)e * Dc * Pc + (size_t)(m0 + m) * Pc + tid] = acc;
        }
    }
}

// ---------------- kP2: z-branch per (b,e) ------------------------------------
__global__ __launch_bounds__(128) void kP2_z(const float* __restrict__ Wc,
                                             const float* __restrict__ bc,
                                             const float* __restrict__ Wp,
                                             const float* __restrict__ bp) {
    int r = blockIdx.x;      // b*8+e
    int e = r & 7;
    int tid = threadIdx.x;
    __shared__ float zp[Dc + 2 * PADc];
    __shared__ float cz[Dc];
    __shared__ float swz[Kc];
    __shared__ float s_bc;

    const float* zr = g_atto + (size_t)r * Dc;
    for (int i = tid; i < Dc + 2 * PADc; i += 128) {
        bool in = (i >= PADc) && (i < Dc + PADc);
        zp[i] = in ? zr[i - PADc] : 0.f;
    }
    if (tid < Kc) swz[tid] = Wc[e * 2 * Kc + Kc + tid];
    if (tid == 0) s_bc = bc[e];
    __syncthreads();
    #pragma unroll
    for (int jj = 0; jj < 4; jj++) {
        int l = tid * 4 + jj;
        if (l < Dc) {
            float acc = s_bc;
            #pragma unroll
            for (int k = 0; k < Kc; k++) acc += swz[k] * zp[l + k];
            cz[l] = acc;
        }
    }
    __syncthreads();
    if (tid < Pc) {
        const float* wp = Wp + (size_t)e * Dc * Pc + tid;
        float a0 = bp[e * Pc + tid], a1 = 0, a2 = 0, a3 = 0;
        for (int l = 0; l < Dc; l += 4) {
            a0 += cz[l + 0] * wp[(size_t)(l + 0) * Pc];
            a1 += cz[l + 1] * wp[(size_t)(l + 1) * Pc];
            a2 += cz[l + 2] * wp[(size_t)(l + 2) * Pc];
            a3 += cz[l + 3] * wp[(size_t)(l + 3) * Pc];
        }
        g_zlin[r * Pc + tid] = (a0 + a1) + (a2 + a3);
    }
}

// ---------------- k11: grouped GEMM  out = x @ Wxe[e] + zlin -----------------
__global__ __launch_bounds__(256) void k11_lin(const float* __restrict__ x,
                                               float* __restrict__ out) {
    int e = blockIdx.y;
    int c = blockIdx.x;
    int off0 = g_off[e], off1 = g_off[e + 1];
    int base = off0 + c * 64;
    if (base >= off1) return;

    __shared__ float sX[64][33];     // [tok][k]
    __shared__ float sW[32][97];     // [k][p]
    __shared__ int   stok[64];
    __shared__ int   sval[64];
    int tid = threadIdx.x;
    if (tid < 64) {
        int s = base + tid;
        int v = (s < off1) ? 1 : 0;
        stok[tid] = v ? g_tok[s] : 0;
        sval[tid] = v;
    }
    __syncthreads();

    int ty = tid >> 4, tx = tid & 15;  // 16 tok-groups(4) x 16 p-lanes(6)
    float acc[4][6] = {};
    const float4* x4 = (const float4*)x;
    const float4* w4 = (const float4*)(g_wx + (size_t)e * Dc * Pc);
    for (int kk = 0; kk < Dc; kk += 32) {
        // x tile: 64 tok x 32 k (512 float4 / 256 thr = 2)
        #pragma unroll
        for (int jj = 0; jj < 2; jj++) {
            int id = tid + jj * 256;
            int rr = id >> 3, k4 = id & 7;
            float4 v = sval[rr] ? x4[((size_t)stok[rr] * Dc + kk) / 4 + k4]
                                : make_float4(0.f, 0.f, 0.f, 0.f);
            sX[rr][k4 * 4 + 0] = v.x;
            sX[rr][k4 * 4 + 1] = v.y;
            sX[rr][k4 * 4 + 2] = v.z;
            sX[rr][k4 * 4 + 3] = v.w;
        }
        // W tile: 32 k x 96 p (768 float4 / 256 thr = 3)
        #pragma unroll
        for (int jj = 0; jj < 3; jj++) {
            int id = tid + jj * 256;
            int k = id / 24, p4 = id - k * 24;
            float4 v = w4[((size_t)(kk + k) * Pc) / 4 + p4];
            sW[k][p4 * 4 + 0] = v.x;
            sW[k][p4 * 4 + 1] = v.y;
            sW[k][p4 * 4 + 2] = v.z;
            sW[k][p4 * 4 + 3] = v.w;
        }
        __syncthreads();
        #pragma unroll
        for (int k = 0; k < 32; k++) {
            float w[6], a[4];
            #pragma unroll
            for (int jj = 0; jj < 6; jj++) w[jj] = sW[k][tx * 6 + jj];
            #pragma unroll
            for (int i = 0; i < 4; i++) a[i] = sX[ty * 4 + i][k];
            #pragma unroll
            for (int i = 0; i < 4; i++)
                #pragma unroll
                for (int jj = 0; jj < 6; jj++) acc[i][jj] += a[i] * w[jj];
        }
        __syncthreads();
    }
    #pragma unroll
    for (int i = 0; i < 4; i++) {
        int rr = ty * 4 + i;
        if (sval[rr]) {
            int tt = stok[rr];
            int zb = ((tt >> 9) * Ec + e) * Pc;
            #pragma unroll
            for (int jj = 0; jj < 6; jj++)
                out[(size_t)tt * Pc + tx * 6 + jj] = acc[i][jj] + g_zlin[zb + tx * 6 + jj];
        }
    }
}

// ---------------- launcher ---------------------------------------------------
extern "C" void kernel_launch(void* const* d_in, const int* in_sizes, int n_in,
                              void* d_out, int out_size) {
    const float* x      = (const float*)d_in[0];
    const float* router = (const float*)d_in[1];
    const float* Wq     = (const float*)d_in[2];
    const float* bq     = (const float*)d_in[3];
    const float* Wk     = (const float*)d_in[4];
    const float* bk     = (const float*)d_in[5];
    const float* Wv     = (const float*)d_in[6];
    const float* bv     = (const float*)d_in[7];
    const float* Wo     = (const float*)d_in[8];
    const float* bo     = (const float*)d_in[9];
    const float* Wc     = (const float*)d_in[10];
    const float* bc     = (const float*)d_in[11];
    const float* Wp     = (const float*)d_in[12];
    const float* bp     = (const float*)d_in[13];
    float* out = (float*)d_out;

    kP1_fold<<<dim3(Ec, 16), 128>>>(Wc, Wp);
    kA_qk<<<EHc, 256>>>(router, Wq, bq, Wk, bk);
    k3_scores<<<BNc / 64, 128>>>(x);
    k4_softmax<<<Bc * EHc, 256>>>();
    k5_y<<<dim3(Dc / 64, Bc), 128>>>(x);
    k6_att<<<dim3(16, 8), 128>>>(Wv, bv);
    k7_oproj<<<dim3(16, 8), 128>>>(Wo, bo);
    k9_route<<<dim3(Nc / 64, Bc), 64>>>(x);
    kg2_scan<<<1, 256>>>();
    kg3_scatter<<<256, 64>>>();
    kP2_z<<<Bc * Ec, 128>>>(Wc, bc, Wp, bp);
    k11_lin<<<dim3(BNc / 64, Ec), 256>>>(x, out);
}